// round 8
// baseline (speedup 1.0000x reference)
#include <cuda_runtime.h>
#include <cuda_fp16.h>
#include <math.h>
#include <stdint.h>

#define D 128
#define N_MAX 16384
#define BM 128
#define BNT 128
#define THREADS 512
#define JCHUNKS 8

// Scratch (allocation-free rule: __device__ globals)
__device__ __half g_z1h[N_MAX * D];   // fp16, pre-scaled by 2/ln2
__device__ __half g_z2h[N_MAX * D];   // fp16
__device__ float g_denom[N_MAX];
__device__ float g_pos[N_MAX];

// padded smem row stride: 128 fp16 + 8 pad = 136 elems = 272 bytes
#define SROW 272
#define TILE_BYTES (128 * SROW)          // 34816
#define OFF_A 0
#define OFF_B0 TILE_BYTES                // 3 rotating B buffers
#define OFF_RED (OFF_B0 + 3 * TILE_BYTES)
#define SMEM_BYTES (OFF_RED + 128 * 4)   // ~140KB

__device__ __forceinline__ uint32_t smem_u32(const void* p) {
    uint32_t a;
    asm("{ .reg .u64 t; cvta.to.shared.u64 t, %1; cvt.u32.u64 %0, t; }"
        : "=r"(a) : "l"(p));
    return a;
}

__device__ __forceinline__ float warp_sum(float v) {
    #pragma unroll
    for (int off = 16; off > 0; off >>= 1)
        v += __shfl_xor_sync(0xFFFFFFFFu, v, off);
    return v;
}

// One warp per row: fp32 normalize, exact fp32 pos, fp16 copies; zero g_denom.
__global__ void norm_kernel(const float* __restrict__ z1,
                            const float* __restrict__ z2, int N) {
    int warp = (blockIdx.x * blockDim.x + threadIdx.x) >> 5;
    int lane = threadIdx.x & 31;
    if (warp >= N) return;

    const float4 a = ((const float4*)(z1 + (size_t)warp * D))[lane];
    const float4 b = ((const float4*)(z2 + (size_t)warp * D))[lane];

    float sa = a.x * a.x + a.y * a.y + a.z * a.z + a.w * a.w;
    float sb = b.x * b.x + b.y * b.y + b.z * b.z + b.w * b.w;
    sa = warp_sum(sa);
    sb = warp_sum(sb);

    float inva = 1.0f / fmaxf(sqrtf(sa), 1e-12f);
    float invb = 1.0f / fmaxf(sqrtf(sb), 1e-12f);

    float4 an = make_float4(a.x * inva, a.y * inva, a.z * inva, a.w * inva);
    float4 bn = make_float4(b.x * invb, b.y * invb, b.z * invb, b.w * invb);

    // bake exponent scale 2/ln2 into A so epilogue is a bare ex2.approx
    const float S = 2.8853900817779268f;
    __half2 a01 = __floats2half2_rn(an.x * S, an.y * S);
    __half2 a23 = __floats2half2_rn(an.z * S, an.w * S);
    __half2 b01 = __floats2half2_rn(bn.x, bn.y);
    __half2 b23 = __floats2half2_rn(bn.z, bn.w);

    uint2 pa, pb;
    pa.x = *(uint32_t*)&a01; pa.y = *(uint32_t*)&a23;
    pb.x = *(uint32_t*)&b01; pb.y = *(uint32_t*)&b23;
    ((uint2*)(g_z1h + (size_t)warp * D))[lane] = pa;
    ((uint2*)(g_z2h + (size_t)warp * D))[lane] = pb;

    float d = an.x * bn.x + an.y * bn.y + an.z * bn.z + an.w * bn.w;
    d = warp_sum(d);
    if (lane == 0) {
        g_pos[warp] = 2.0f * d;
        g_denom[warp] = 0.0f;
    }
}

__device__ __forceinline__ void ldsm_x4(uint32_t (&r)[4], uint32_t addr) {
    asm volatile("ldmatrix.sync.aligned.m8n8.x4.shared.b16 {%0,%1,%2,%3}, [%4];"
                 : "=r"(r[0]), "=r"(r[1]), "=r"(r[2]), "=r"(r[3]) : "r"(addr));
}

// fp16 in, fp16 accum: C/D fragments are 2 regs of f16x2
__device__ __forceinline__ void hmma_f16acc(uint32_t (&c)[2], const uint32_t (&a)[4],
                                            uint32_t b0, uint32_t b1) {
    asm volatile(
        "mma.sync.aligned.m16n8k16.row.col.f16.f16.f16.f16 "
        "{%0,%1}, {%2,%3,%4,%5}, {%6,%7}, {%0,%1};"
        : "+r"(c[0]), "+r"(c[1])
        : "r"(a[0]), "r"(a[1]), "r"(a[2]), "r"(a[3]), "r"(b0), "r"(b1));
}

__device__ __forceinline__ void cp16(uint32_t dst, const void* src) {
    asm volatile("cp.async.cg.shared.global [%0], [%1], 16;"
                 :: "r"(dst), "l"(src) : "memory");
}

// ---------------------------------------------------------------------------
// FP16-accum HMMA GEMM + fused exp/rowsum.
// Grid (N/128 row-tiles, JCHUNKS j-chunks), 512 threads (16 warps 4x4).
// Warp tile 32x32. A persistent; B triple-buffered (1 barrier/tile).
// Double accumulator sets: epilogue of tile t-1 overlaps k-loop of tile t,
// so the HMMA stream never drains behind the MUFU/FADD epilogue.
// ---------------------------------------------------------------------------
__global__ void __launch_bounds__(THREADS, 1)
gemm_hmma16_kernel(int N) {
    extern __shared__ char smem[];
    const uint32_t sb = smem_u32(smem);
    const int tid = threadIdx.x;
    const int wid = tid >> 5;
    const int lane = tid & 31;
    const int warp_m = wid >> 2;      // 0..3
    const int warp_n = wid & 3;       // 0..3
    const int i0 = blockIdx.x * BM;
    const int T = (N / BNT) / JCHUNKS;   // 16 tiles per chunk
    const int jt0 = blockIdx.y * T;

    // Load A tile (128x128 fp16) into padded smem.
    {
        const uint4* A4 = (const uint4*)(g_z1h + (size_t)i0 * D);
        #pragma unroll
        for (int t = 0; t < 4; ++t) {
            int idx = tid + t * THREADS;        // 0..2047
            int r = idx >> 4, c = idx & 15;
            *(uint4*)(smem + OFF_A + r * SROW + c * 16) = A4[idx];
        }
    }

    // Prologue: tiles jt0 -> buf0, jt0+1 -> buf1
    #pragma unroll
    for (int pt = 0; pt < 2; ++pt) {
        const char* B = (const char*)(g_z2h + (size_t)(jt0 + pt) * BNT * D);
        uint32_t dst = sb + OFF_B0 + (uint32_t)pt * TILE_BYTES;
        #pragma unroll
        for (int t = 0; t < 4; ++t) {
            int idx = tid + t * THREADS;
            int r = idx >> 4, c = idx & 15;
            cp16(dst + r * SROW + c * 16, B + (size_t)r * 256 + c * 16);
        }
        asm volatile("cp.async.commit_group;" ::: "memory");
    }

    const uint32_t a_base = sb + OFF_A +
        (uint32_t)(warp_m * 32 + (lane & 15)) * SROW + (uint32_t)((lane >> 4) * 16);
    const uint32_t b_lane_off =
        (uint32_t)(warp_n * 32 + (lane & 15)) * SROW + (uint32_t)((lane >> 4) * 16);

    uint32_t c[2][2][4][2];   // [acc set][mf][nf][reg]
    #pragma unroll
    for (int p = 0; p < 2; ++p)
        #pragma unroll
        for (int mf = 0; mf < 2; ++mf)
            #pragma unroll
            for (int nf = 0; nf < 4; ++nf) { c[p][mf][nf][0] = 0u; c[p][mf][nf][1] = 0u; }

    float rs[4] = {0.f, 0.f, 0.f, 0.f};

    for (int t = 0; t < T; ++t) {
        const int p = t & 1;

        if (t < T - 1) {
            asm volatile("cp.async.wait_group 1;" ::: "memory");
        } else {
            asm volatile("cp.async.wait_group 0;" ::: "memory");
        }
        __syncthreads();   // buf t%3 visible to all; buf (t+2)%3 free

        if (t + 2 < T) {
            const char* B = (const char*)(g_z2h + (size_t)(jt0 + t + 2) * BNT * D);
            uint32_t dst = sb + OFF_B0 + (uint32_t)((t + 2) % 3) * TILE_BYTES;
            #pragma unroll
            for (int u = 0; u < 4; ++u) {
                int idx = tid + u * THREADS;
                int r = idx >> 4, ch = idx & 15;
                cp16(dst + r * SROW + ch * 16, B + (size_t)r * 256 + ch * 16);
            }
            asm volatile("cp.async.commit_group;" ::: "memory");
        }

        const uint32_t b_base = sb + OFF_B0 + (uint32_t)(t % 3) * TILE_BYTES + b_lane_off;

        #pragma unroll
        for (int kk = 0; kk < 8; ++kk) {
            const uint32_t koff = (uint32_t)kk * 32;
            uint32_t a[2][4];
            #pragma unroll
            for (int mf = 0; mf < 2; ++mf)
                ldsm_x4(a[mf], a_base + (uint32_t)(mf * 16) * SROW + koff);
            uint32_t bm[2][4];
            #pragma unroll
            for (int nf2 = 0; nf2 < 2; ++nf2)
                ldsm_x4(bm[nf2], b_base + (uint32_t)(nf2 * 16) * SROW + koff);

            #pragma unroll
            for (int mf = 0; mf < 2; ++mf)
                #pragma unroll
                for (int nf = 0; nf < 4; ++nf)
                    hmma_f16acc(c[p][mf][nf], a[mf],
                                bm[nf >> 1][nf & 1], bm[nf >> 1][(nf & 1) + 2]);
        }

        // deferred epilogue for tile t-1 (acc set 1-p): rowsum += 2^c
        if (t > 0) {
            #pragma unroll
            for (int mf = 0; mf < 2; ++mf) {
                float lo = 0.f, hi = 0.f;
                #pragma unroll
                for (int nf = 0; nf < 4; ++nf) {
                    float2 f0 = __half22float2(*(__half2*)&c[1 - p][mf][nf][0]);
                    float2 f1 = __half22float2(*(__half2*)&c[1 - p][mf][nf][1]);
                    float e0, e1, e2, e3;
                    asm("ex2.approx.f32 %0, %1;" : "=f"(e0) : "f"(f0.x));
                    asm("ex2.approx.f32 %0, %1;" : "=f"(e1) : "f"(f0.y));
                    asm("ex2.approx.f32 %0, %1;" : "=f"(e2) : "f"(f1.x));
                    asm("ex2.approx.f32 %0, %1;" : "=f"(e3) : "f"(f1.y));
                    lo += e0 + e1;
                    hi += e2 + e3;
                    c[1 - p][mf][nf][0] = 0u;
                    c[1 - p][mf][nf][1] = 0u;
                }
                rs[mf * 2 + 0] += lo;
                rs[mf * 2 + 1] += hi;
            }
        }
    }

    // final epilogue for tile T-1 (acc set (T-1)&1)
    {
        const int p = (T - 1) & 1;
        #pragma unroll
        for (int mf = 0; mf < 2; ++mf) {
            float lo = 0.f, hi = 0.f;
            #pragma unroll
            for (int nf = 0; nf < 4; ++nf) {
                float2 f0 = __half22float2(*(__half2*)&c[p][mf][nf][0]);
                float2 f1 = __half22float2(*(__half2*)&c[p][mf][nf][1]);
                float e0, e1, e2, e3;
                asm("ex2.approx.f32 %0, %1;" : "=f"(e0) : "f"(f0.x));
                asm("ex2.approx.f32 %0, %1;" : "=f"(e1) : "f"(f0.y));
                asm("ex2.approx.f32 %0, %1;" : "=f"(e2) : "f"(f1.x));
                asm("ex2.approx.f32 %0, %1;" : "=f"(e3) : "f"(f1.y));
                lo += e0 + e1;
                hi += e2 + e3;
            }
            rs[mf * 2 + 0] += lo;
            rs[mf * 2 + 1] += hi;
        }
    }

    // reduce rs across the 4 lanes of each quad (same row group)
    #pragma unroll
    for (int i = 0; i < 4; ++i) {
        rs[i] += __shfl_xor_sync(0xFFFFFFFFu, rs[i], 1);
        rs[i] += __shfl_xor_sync(0xFFFFFFFFu, rs[i], 2);
    }

    float* red = (float*)(smem + OFF_RED);
    __syncthreads();
    if (tid < 128) red[tid] = 0.f;
    __syncthreads();
    if ((lane & 3) == 0) {
        #pragma unroll
        for (int mf = 0; mf < 2; ++mf) {
            #pragma unroll
            for (int sub = 0; sub < 2; ++sub) {
                int row = warp_m * 32 + mf * 16 + sub * 8 + (lane >> 2);
                atomicAdd(&red[row], rs[mf * 2 + sub]);
            }
        }
    }
    __syncthreads();
    if (tid < 128) atomicAdd(&g_denom[i0 + tid], red[tid]);
}

__global__ void loss_kernel(float* __restrict__ out, int N) {
    __shared__ float smr[256];
    float s = 0.f;
    for (int i = threadIdx.x; i < N; i += 256)
        s += logf(g_denom[i] + 1e-8f) - g_pos[i];
    smr[threadIdx.x] = s;
    __syncthreads();
    #pragma unroll
    for (int off = 128; off > 0; off >>= 1) {
        if (threadIdx.x < off) smr[threadIdx.x] += smr[threadIdx.x + off];
        __syncthreads();
    }
    if (threadIdx.x == 0) out[0] = smr[0] / (float)N;
}

extern "C" void kernel_launch(void* const* d_in, const int* in_sizes, int n_in,
                              void* d_out, int out_size) {
    const float* z1 = (const float*)d_in[0];
    const float* z2 = (const float*)d_in[1];
    float* out = (float*)d_out;
    const int N = in_sizes[0] / D;  // 16384

    cudaFuncSetAttribute(gemm_hmma16_kernel,
                         cudaFuncAttributeMaxDynamicSharedMemorySize,
                         (int)SMEM_BYTES);

    norm_kernel<<<(N + 7) / 8, 256>>>(z1, z2, N);
    dim3 grid(N / BM, JCHUNKS);
    gemm_hmma16_kernel<<<grid, THREADS, SMEM_BYTES>>>(N);
    loss_kernel<<<1, 256>>>(out, N);
}

// round 9
// speedup vs baseline: 1.3909x; 1.3909x over previous
#include <cuda_runtime.h>
#include <cuda_fp16.h>
#include <math.h>
#include <stdint.h>

#define D 128
#define N_MAX 16384
#define BM 128
#define BNT 128
#define THREADS 512
#define JCHUNKS 8

// Scratch (allocation-free rule: __device__ globals)
__device__ __half g_z1h[N_MAX * D];   // fp16, pre-scaled by 2/ln2
__device__ __half g_z2h[N_MAX * D];   // fp16
__device__ float g_denom[N_MAX];
__device__ float g_pos[N_MAX];

// padded smem row stride: 128 fp16 + 8 pad = 136 elems = 272 bytes
#define SROW 272
#define TILE_BYTES (128 * SROW)          // 34816
#define OFF_A 0
#define OFF_B0 TILE_BYTES
#define OFF_B1 (2 * TILE_BYTES)
#define OFF_RED (3 * TILE_BYTES)
#define SMEM_BYTES (OFF_RED + 128 * 4)

__device__ __forceinline__ uint32_t smem_u32(const void* p) {
    uint32_t a;
    asm("{ .reg .u64 t; cvta.to.shared.u64 t, %1; cvt.u32.u64 %0, t; }"
        : "=r"(a) : "l"(p));
    return a;
}

__device__ __forceinline__ float warp_sum(float v) {
    #pragma unroll
    for (int off = 16; off > 0; off >>= 1)
        v += __shfl_xor_sync(0xFFFFFFFFu, v, off);
    return v;
}

// One warp per row: fp32 normalize, exact fp32 pos, fp16 copies; zero g_denom.
__global__ void norm_kernel(const float* __restrict__ z1,
                            const float* __restrict__ z2, int N) {
    int warp = (blockIdx.x * blockDim.x + threadIdx.x) >> 5;
    int lane = threadIdx.x & 31;
    if (warp >= N) return;

    const float4 a = ((const float4*)(z1 + (size_t)warp * D))[lane];
    const float4 b = ((const float4*)(z2 + (size_t)warp * D))[lane];

    float sa = a.x * a.x + a.y * a.y + a.z * a.z + a.w * a.w;
    float sb = b.x * b.x + b.y * b.y + b.z * b.z + b.w * b.w;
    sa = warp_sum(sa);
    sb = warp_sum(sb);

    float inva = 1.0f / fmaxf(sqrtf(sa), 1e-12f);
    float invb = 1.0f / fmaxf(sqrtf(sb), 1e-12f);

    float4 an = make_float4(a.x * inva, a.y * inva, a.z * inva, a.w * inva);
    float4 bn = make_float4(b.x * invb, b.y * invb, b.z * invb, b.w * invb);

    // bake exponent scale 2/ln2 into A so epilogue is a bare ex2.approx
    const float S = 2.8853900817779268f;
    __half2 a01 = __floats2half2_rn(an.x * S, an.y * S);
    __half2 a23 = __floats2half2_rn(an.z * S, an.w * S);
    __half2 b01 = __floats2half2_rn(bn.x, bn.y);
    __half2 b23 = __floats2half2_rn(bn.z, bn.w);

    uint2 pa, pb;
    pa.x = *(uint32_t*)&a01; pa.y = *(uint32_t*)&a23;
    pb.x = *(uint32_t*)&b01; pb.y = *(uint32_t*)&b23;
    ((uint2*)(g_z1h + (size_t)warp * D))[lane] = pa;
    ((uint2*)(g_z2h + (size_t)warp * D))[lane] = pb;

    float d = an.x * bn.x + an.y * bn.y + an.z * bn.z + an.w * bn.w;
    d = warp_sum(d);
    if (lane == 0) {
        g_pos[warp] = 2.0f * d;
        g_denom[warp] = 0.0f;
    }
}

__device__ __forceinline__ void ldsm_x4(uint32_t (&r)[4], uint32_t addr) {
    asm volatile("ldmatrix.sync.aligned.m8n8.x4.shared.b16 {%0,%1,%2,%3}, [%4];"
                 : "=r"(r[0]), "=r"(r[1]), "=r"(r[2]), "=r"(r[3]) : "r"(addr));
}

// fp16 in, fp16 accum: C/D fragments are 2 regs of f16x2
__device__ __forceinline__ void hmma_f16acc(uint32_t (&c)[2], const uint32_t (&a)[4],
                                            uint32_t b0, uint32_t b1) {
    asm volatile(
        "mma.sync.aligned.m16n8k16.row.col.f16.f16.f16.f16 "
        "{%0,%1}, {%2,%3,%4,%5}, {%6,%7}, {%0,%1};"
        : "+r"(c[0]), "+r"(c[1])
        : "r"(a[0]), "r"(a[1]), "r"(a[2]), "r"(a[3]), "r"(b0), "r"(b1));
}

__device__ __forceinline__ void cp16(uint32_t dst, const void* src) {
    asm volatile("cp.async.cg.shared.global [%0], [%1], 16;"
                 :: "r"(dst), "l"(src) : "memory");
}

// One tile's k-loop accumulating into `acc`, with the epilogue of the
// PREVIOUS tile (`cprev`) interleaved one fragment-group per kk step.
// All register-array indices are compile-time (no spills).
__device__ __forceinline__ void tile_step(
    uint32_t (&acc)[2][4][2], uint32_t (&cprev)[2][4][2],
    uint32_t a_base, uint32_t b_base, float (&rs)[4]) {
    #pragma unroll
    for (int kk = 0; kk < 8; ++kk) {
        const uint32_t koff = (uint32_t)kk * 32;
        uint32_t a[2][4];
        #pragma unroll
        for (int mf = 0; mf < 2; ++mf)
            ldsm_x4(a[mf], a_base + (uint32_t)(mf * 16) * SROW + koff);
        uint32_t bm[2][4];
        #pragma unroll
        for (int nf2 = 0; nf2 < 2; ++nf2)
            ldsm_x4(bm[nf2], b_base + (uint32_t)(nf2 * 16) * SROW + koff);

        #pragma unroll
        for (int mf = 0; mf < 2; ++mf)
            #pragma unroll
            for (int nf = 0; nf < 4; ++nf)
                hmma_f16acc(acc[mf][nf], a[mf],
                            bm[nf >> 1][nf & 1], bm[nf >> 1][(nf & 1) + 2]);

        // deferred epilogue chunk: fragment group g = kk of previous tile
        {
            const int mf = kk >> 2, nf = kk & 3;
            float2 f0 = __half22float2(*(__half2*)&cprev[mf][nf][0]);
            float2 f1 = __half22float2(*(__half2*)&cprev[mf][nf][1]);
            float e0, e1, e2, e3;
            asm("ex2.approx.f32 %0, %1;" : "=f"(e0) : "f"(f0.x));
            asm("ex2.approx.f32 %0, %1;" : "=f"(e1) : "f"(f0.y));
            asm("ex2.approx.f32 %0, %1;" : "=f"(e2) : "f"(f1.x));
            asm("ex2.approx.f32 %0, %1;" : "=f"(e3) : "f"(f1.y));
            rs[mf * 2 + 0] += e0 + e1;
            rs[mf * 2 + 1] += e2 + e3;
            cprev[mf][nf][0] = 0u;
            cprev[mf][nf][1] = 0u;
        }
    }
}

// ---------------------------------------------------------------------------
// FP16-accum HMMA GEMM + fused deferred exp/rowsum.
// Grid (N/128 row-tiles, JCHUNKS j-chunks), 512 threads (16 warps 4x4).
// Warp tile 32x32. A persistent; B double-buffered; loop unrolled x2 with
// static accumulator sets c0/c1. Tile 0's bogus epilogue of zeros adds
// exactly 1024 per row total (8 chunks x 128); subtracted in loss_kernel.
// ---------------------------------------------------------------------------
__global__ void __launch_bounds__(THREADS, 1)
gemm_hmma16_kernel(int N) {
    extern __shared__ char smem[];
    const uint32_t sb = smem_u32(smem);
    const int tid = threadIdx.x;
    const int wid = tid >> 5;
    const int lane = tid & 31;
    const int warp_m = wid >> 2;      // 0..3
    const int warp_n = wid & 3;       // 0..3
    const int i0 = blockIdx.x * BM;
    const int T = (N / BNT) / JCHUNKS;   // 16 tiles per chunk (even)
    const int jt0 = blockIdx.y * T;

    // Load A tile (128x128 fp16) into padded smem.
    {
        const uint4* A4 = (const uint4*)(g_z1h + (size_t)i0 * D);
        #pragma unroll
        for (int t = 0; t < 4; ++t) {
            int idx = tid + t * THREADS;        // 0..2047
            int r = idx >> 4, c = idx & 15;
            *(uint4*)(smem + OFF_A + r * SROW + c * 16) = A4[idx];
        }
    }

    // Prologue: B tile jt0 -> buf0
    {
        const char* B = (const char*)(g_z2h + (size_t)jt0 * BNT * D);
        #pragma unroll
        for (int t = 0; t < 4; ++t) {
            int idx = tid + t * THREADS;
            int r = idx >> 4, c = idx & 15;
            cp16(sb + OFF_B0 + r * SROW + c * 16, B + (size_t)r * 256 + c * 16);
        }
        asm volatile("cp.async.commit_group;" ::: "memory");
    }

    const uint32_t a_base = sb + OFF_A +
        (uint32_t)(warp_m * 32 + (lane & 15)) * SROW + (uint32_t)((lane >> 4) * 16);
    const uint32_t b_lane_off =
        (uint32_t)(warp_n * 32 + (lane & 15)) * SROW + (uint32_t)((lane >> 4) * 16);
    const uint32_t b_base0 = sb + OFF_B0 + b_lane_off;
    const uint32_t b_base1 = sb + OFF_B1 + b_lane_off;

    uint32_t c0[2][4][2], c1[2][4][2];
    #pragma unroll
    for (int mf = 0; mf < 2; ++mf)
        #pragma unroll
        for (int nf = 0; nf < 4; ++nf) {
            c0[mf][nf][0] = 0u; c0[mf][nf][1] = 0u;
            c1[mf][nf][0] = 0u; c1[mf][nf][1] = 0u;
        }

    float rs[4] = {0.f, 0.f, 0.f, 0.f};

    for (int t = 0; t < T; t += 2) {
        // ---- sub-iter A: tile t (buf0, acc c0, epilogue c1 = tile t-1) ----
        __syncthreads();   // everyone done reading buf1
        {   // t+1 < T always (T even, t <= T-2)
            const char* B = (const char*)(g_z2h + (size_t)(jt0 + t + 1) * BNT * D);
            #pragma unroll
            for (int u = 0; u < 4; ++u) {
                int idx = tid + u * THREADS;
                int r = idx >> 4, ch = idx & 15;
                cp16(sb + OFF_B1 + r * SROW + ch * 16, B + (size_t)r * 256 + ch * 16);
            }
            asm volatile("cp.async.commit_group;" ::: "memory");
            asm volatile("cp.async.wait_group 1;" ::: "memory");
        }
        __syncthreads();   // buf0 visible
        tile_step(c0, c1, a_base, b_base0, rs);

        // ---- sub-iter B: tile t+1 (buf1, acc c1, epilogue c0 = tile t) ----
        __syncthreads();   // everyone done reading buf0
        if (t + 2 < T) {
            const char* B = (const char*)(g_z2h + (size_t)(jt0 + t + 2) * BNT * D);
            #pragma unroll
            for (int u = 0; u < 4; ++u) {
                int idx = tid + u * THREADS;
                int r = idx >> 4, ch = idx & 15;
                cp16(sb + OFF_B0 + r * SROW + ch * 16, B + (size_t)r * 256 + ch * 16);
            }
            asm volatile("cp.async.commit_group;" ::: "memory");
            asm volatile("cp.async.wait_group 1;" ::: "memory");
        } else {
            asm volatile("cp.async.wait_group 0;" ::: "memory");
        }
        __syncthreads();   // buf1 visible
        tile_step(c1, c0, a_base, b_base1, rs);
    }

    // final epilogue: c1 holds tile T-1
    #pragma unroll
    for (int mf = 0; mf < 2; ++mf) {
        float lo = 0.f, hi = 0.f;
        #pragma unroll
        for (int nf = 0; nf < 4; ++nf) {
            float2 f0 = __half22float2(*(__half2*)&c1[mf][nf][0]);
            float2 f1 = __half22float2(*(__half2*)&c1[mf][nf][1]);
            float e0, e1, e2, e3;
            asm("ex2.approx.f32 %0, %1;" : "=f"(e0) : "f"(f0.x));
            asm("ex2.approx.f32 %0, %1;" : "=f"(e1) : "f"(f0.y));
            asm("ex2.approx.f32 %0, %1;" : "=f"(e2) : "f"(f1.x));
            asm("ex2.approx.f32 %0, %1;" : "=f"(e3) : "f"(f1.y));
            lo += e0 + e1;
            hi += e2 + e3;
        }
        rs[mf * 2 + 0] += lo;
        rs[mf * 2 + 1] += hi;
    }

    // reduce rs across the 4 lanes of each quad (same row group)
    #pragma unroll
    for (int i = 0; i < 4; ++i) {
        rs[i] += __shfl_xor_sync(0xFFFFFFFFu, rs[i], 1);
        rs[i] += __shfl_xor_sync(0xFFFFFFFFu, rs[i], 2);
    }

    float* red = (float*)(smem + OFF_RED);
    __syncthreads();
    if (tid < 128) red[tid] = 0.f;
    __syncthreads();
    if ((lane & 3) == 0) {
        #pragma unroll
        for (int mf = 0; mf < 2; ++mf) {
            #pragma unroll
            for (int sub = 0; sub < 2; ++sub) {
                int row = warp_m * 32 + mf * 16 + sub * 8 + (lane >> 2);
                atomicAdd(&red[row], rs[mf * 2 + sub]);
            }
        }
    }
    __syncthreads();
    if (tid < 128) atomicAdd(&g_denom[i0 + tid], red[tid]);
}

__global__ void loss_kernel(float* __restrict__ out, int N) {
    __shared__ float smr[256];
    float s = 0.f;
    // subtract the deterministic bogus-first-epilogue contribution:
    // JCHUNKS chunks x 128 cols of ex2(0)=1 per row = 1024 per row.
    const float BOGUS = 128.0f * (float)JCHUNKS;
    for (int i = threadIdx.x; i < N; i += 256)
        s += logf(g_denom[i] - BOGUS + 1e-8f) - g_pos[i];
    smr[threadIdx.x] = s;
    __syncthreads();
    #pragma unroll
    for (int off = 128; off > 0; off >>= 1) {
        if (threadIdx.x < off) smr[threadIdx.x] += smr[threadIdx.x + off];
        __syncthreads();
    }
    if (threadIdx.x == 0) out[0] = smr[0] / (float)N;
}

extern "C" void kernel_launch(void* const* d_in, const int* in_sizes, int n_in,
                              void* d_out, int out_size) {
    const float* z1 = (const float*)d_in[0];
    const float* z2 = (const float*)d_in[1];
    float* out = (float*)d_out;
    const int N = in_sizes[0] / D;  // 16384

    cudaFuncSetAttribute(gemm_hmma16_kernel,
                         cudaFuncAttributeMaxDynamicSharedMemorySize,
                         (int)SMEM_BYTES);

    norm_kernel<<<(N + 7) / 8, 256>>>(z1, z2, N);
    dim3 grid(N / BM, JCHUNKS);
    gemm_hmma16_kernel<<<grid, THREADS, SMEM_BYTES>>>(N);
    loss_kernel<<<1, 256>>>(out, N);
}